// round 1
// baseline (speedup 1.0000x reference)
#include <cuda_runtime.h>
#include <math.h>

#define DIMK 256
#define SEQL 2048
#define NTOK 2049
#define BATCH 2
#define WINW 64
#define KNB 129          // 2*WIN+1
#define HEADS 4
#define RANK 32
#define HR 128           // HEADS*RANK
#define NLAYERS 3
#define EPSV 1e-6f
#define ROWS (BATCH*NTOK) // 4098
#define HID 512

// ---------------- scratch (device globals; no runtime allocation) -------------
__device__ float g_val [ROWS*DIMK];
__device__ float g_val2[ROWS*DIMK];
__device__ float g_state [ROWS];
__device__ float g_state2[ROWS];
__device__ float g_q[ROWS*HR];
__device__ float g_k[ROWS*HR];
__device__ float g_h[ROWS*HID];

__device__ __forceinline__ float sgnf(float x){ return (float)((x>0.f)-(x<0.f)); }
__device__ __forceinline__ float geluf(float x){ return 0.5f*x*(1.f+erff(x*0.70710678118654752440f)); }

// ---------------- embed: tok = emb[id]+pos; val=unit(tok); tstate=tok.Ws+bs ----
__global__ void k_embed(const int* __restrict__ ids, const float* __restrict__ emb,
                        const float* __restrict__ pos, const float* __restrict__ av,
                        const float* __restrict__ as,  const float* __restrict__ Ws,
                        const float* __restrict__ bs){
    __shared__ float s1[8], s2m[8];
    int bi = blockIdx.x / NTOK, n = blockIdx.x % NTOK, d = threadIdx.x;
    float t, traw = 0.f;
    if (n == 0) { t = av[d]; }
    else { int s = n-1; int id = ids[bi*SEQL+s]; t = emb[id*DIMK+d] + pos[s*DIMK+d]; traw = t; }
    float a = t*t, b = traw*Ws[d];
    int lane = d & 31, w = d >> 5;
    #pragma unroll
    for (int o=16;o;o>>=1){ a += __shfl_xor_sync(~0u,a,o); b += __shfl_xor_sync(~0u,b,o); }
    if (lane==0){ s1[w]=a; s2m[w]=b; }
    __syncthreads();
    if (w==0){
        float x = (lane<8)? s1[lane]:0.f, y = (lane<8)? s2m[lane]:0.f;
        #pragma unroll
        for (int o=4;o;o>>=1){ x += __shfl_xor_sync(~0u,x,o); y += __shfl_xor_sync(~0u,y,o); }
        if (lane==0){ s1[0]=x; s2m[0]=y; }
    }
    __syncthreads();
    float norm = sqrtf(s1[0]);
    g_val[(bi*NTOK+n)*DIMK + d] = t / fmaxf(norm, EPSV);
    if (d==0) g_state[bi*NTOK+n] = (n==0) ? as[0] : (s2m[0] + bs[0]);
}

// ---------------- q/k projection: rows x (D -> H*R), 8-row tiles --------------
__global__ void k_qk(const float* __restrict__ U, const float* __restrict__ V, int layer){
    __shared__ __align__(16) float sA[8*DIMK];
    int row0 = blockIdx.x*8;
    for (int e=threadIdx.x; e<8*DIMK; e+=256){
        int row = row0 + (e>>8);
        sA[e] = (row<ROWS) ? g_val[row*DIMK + (e&255)] : 0.f;
    }
    __syncthreads();
    int j = threadIdx.x & 127;
    const float* W = ((threadIdx.x<128)? U : V) + layer*(DIMK*HR);
    float acc[8] = {0,0,0,0,0,0,0,0};
    for (int d=0; d<DIMK; d+=4){
        float w0=W[(d+0)*HR+j], w1=W[(d+1)*HR+j], w2=W[(d+2)*HR+j], w3=W[(d+3)*HR+j];
        #pragma unroll
        for (int i=0;i<8;i++){
            float4 av = *(const float4*)&sA[i*DIMK+d];
            acc[i] = fmaf(av.x,w0, fmaf(av.y,w1, fmaf(av.z,w2, fmaf(av.w,w3, acc[i]))));
        }
    }
    float* out = (threadIdx.x<128)? g_q : g_k;
    #pragma unroll
    for (int i=0;i<8;i++){ int row=row0+i; if (row<ROWS) out[row*HR+j] = acc[i]; }
}

// ---------------- fused windowed attention, 8 tokens per block ----------------
#define SM_K (144*132)
#define SM_Q (8*HR)
#define SM_S (8*132)
#define ATTN_SMEM_FLOATS (SM_K + SM_Q + SM_S + 144 + 8 + 8)

__global__ void k_attn(){
    extern __shared__ __align__(16) float sm[];
    float*    sK   = sm;               // [144][132] padded keys
    float*    sQ   = sK + SM_K;        // [8][128]
    float*    sS   = sQ + SM_Q;        // [8][132] scores -> weights
    float*    sSt  = sS + SM_S;        // [144] neighbor states
    float*    sSum = sSt + 144;        // [8] norm^2
    unsigned* sMax = (unsigned*)(sSum + 8); // [8] max|dval|
    int bi = blockIdx.y;
    int t0 = blockIdx.x*8;
    int tid = threadIdx.x;
    int nvalid = min(8, NTOK - t0);
    int base = t0 - WINW;

    const float* kb = g_k + bi*NTOK*HR;
    for (int e=tid; e<144*HR; e+=256){
        int r = e>>7;
        int cl = min(max(base+r,0), NTOK-1);
        sK[r*132 + (e&127)] = kb[cl*HR + (e&127)];
    }
    const float* qb = g_q + bi*NTOK*HR;
    for (int e=tid; e<8*HR; e+=256){
        int n = t0 + (e>>7);
        sQ[e] = (n<NTOK) ? qb[n*HR + (e&127)] : 0.f;
    }
    for (int r=tid; r<144; r+=256){
        int cl = min(max(base+r,0), NTOK-1);
        sSt[r] = g_state[bi*NTOK + cl];
    }
    if (tid<8){ sSum[tid]=0.f; sMax[tid]=0u; }
    __syncthreads();

    // scores: s[i][jo] = max_h (q_i . k_{i+jo}) / sqrt(R)
    for (int p=tid; p<nvalid*KNB; p+=256){
        int i = p/KNB, jo = p - i*KNB;
        const float* qq = sQ + i*HR;
        const float* kk = sK + (i+jo)*132;
        float best = -INFINITY;
        #pragma unroll
        for (int h=0; h<HEADS; h++){
            float s = 0.f;
            #pragma unroll
            for (int r4=0; r4<RANK; r4+=4){
                float4 qv = *(const float4*)&qq[h*RANK+r4];
                float4 kv = *(const float4*)&kk[h*RANK+r4];
                s = fmaf(qv.x,kv.x, fmaf(qv.y,kv.y, fmaf(qv.z,kv.z, fmaf(qv.w,kv.w, s))));
            }
            best = fmaxf(best, s);
        }
        sS[i*132+jo] = best * 0.17677669529663687f;  // 1/sqrt(32)
    }
    __syncthreads();

    // per-token signed softmax (warp w owns token t0+w) + dstate
    int w = tid>>5, lane = tid&31;
    if (w < nvalid){
        int n = t0 + w;
        float m = -INFINITY;
        for (int jo=lane; jo<KNB; jo+=32){
            int ab = n - WINW + jo;
            float s = sS[w*132+jo];
            float a = (ab>=0 && ab<NTOK) ? fabsf(s) : -INFINITY;
            m = fmaxf(m, a);
        }
        #pragma unroll
        for (int o=16;o;o>>=1) m = fmaxf(m, __shfl_xor_sync(~0u,m,o));
        float sum = 0.f, wv[5];
        int c = 0;
        for (int jo=lane; jo<KNB; jo+=32, c++){
            int ab = n - WINW + jo;
            bool v = (ab>=0 && ab<NTOK);
            float s = sS[w*132+jo];
            float e = v ? expf(fabsf(s)-m) : 0.f;
            sum += e;
            wv[c] = v ? sgnf(s)*e : 0.f;
        }
        #pragma unroll
        for (int o=16;o;o>>=1) sum += __shfl_xor_sync(~0u,sum,o);
        float inv = 1.f/sum, ds = 0.f;
        c = 0;
        for (int jo=lane; jo<KNB; jo+=32, c++){
            float wg = wv[c]*inv;
            sS[w*132+jo] = wg;
            ds += wg * sSt[w+jo];
        }
        #pragma unroll
        for (int o=16;o;o>>=1) ds += __shfl_xor_sync(~0u,ds,o);
        if (lane==0) g_state2[bi*NTOK+n] = g_state[bi*NTOK+n] + ds;
    }
    __syncthreads();

    // dval: thread owns column d, streams 137 neighbor val rows once
    int d = tid;
    float acc[8] = {0,0,0,0,0,0,0,0};
    const float* vb = g_val + bi*NTOK*DIMK;
    int rmax = nvalid - 1 + 2*WINW;
    for (int r=0; r<=rmax; r++){
        int cl = min(max(base+r,0), NTOK-1);
        float v = vb[cl*DIMK + d];
        #pragma unroll
        for (int i=0;i<8;i++){
            int jo = r - i;
            if (jo>=0 && jo<KNB) acc[i] = fmaf(sS[i*132+jo], v, acc[i]);
        }
    }

    // epilogue: updated = val + dval; conditional unit-norm (touched)
    float upd[8];
    for (int i=0; i<nvalid; i++){
        int n = t0 + i;
        upd[i] = vb[n*DIMK+d] + acc[i];
        float s2 = upd[i]*upd[i];
        float am = fabsf(acc[i]);
        #pragma unroll
        for (int o=16;o;o>>=1){ s2 += __shfl_xor_sync(~0u,s2,o); am = fmaxf(am, __shfl_xor_sync(~0u,am,o)); }
        if (lane==0){ atomicAdd(&sSum[i], s2); atomicMax(&sMax[i], __float_as_uint(am)); }
    }
    __syncthreads();
    float* v2 = g_val2 + bi*NTOK*DIMK;
    for (int i=0; i<nvalid; i++){
        int n = t0 + i;
        bool touched = __uint_as_float(sMax[i]) > 0.f;
        float o = touched ? upd[i]/fmaxf(sqrtf(sSum[i]), EPSV) : upd[i];
        v2[n*DIMK+d] = o;
    }
}

// ---------------- batch-global signed softmax over state ----------------------
__global__ void k_state_sm(){
    __shared__ float sred[8];
    int bi = blockIdx.x, tid = threadIdx.x;
    const float* in = g_state2 + bi*NTOK;
    float m = -INFINITY;
    for (int n=tid; n<NTOK; n+=256) m = fmaxf(m, fabsf(in[n]));
    int lane = tid&31, w = tid>>5;
    #pragma unroll
    for (int o=16;o;o>>=1) m = fmaxf(m, __shfl_xor_sync(~0u,m,o));
    if (lane==0) sred[w] = m;
    __syncthreads();
    if (w==0){ float x=(lane<8)?sred[lane]:-INFINITY;
        #pragma unroll
        for (int o=4;o;o>>=1) x = fmaxf(x, __shfl_xor_sync(~0u,x,o));
        if (lane==0) sred[0]=x; }
    __syncthreads();
    m = sred[0];
    __syncthreads();
    float sum = 0.f;
    for (int n=tid; n<NTOK; n+=256) sum += expf(fabsf(in[n]) - m);
    #pragma unroll
    for (int o=16;o;o>>=1) sum += __shfl_xor_sync(~0u,sum,o);
    if (lane==0) sred[w] = sum;
    __syncthreads();
    if (w==0){ float x=(lane<8)?sred[lane]:0.f;
        #pragma unroll
        for (int o=4;o;o>>=1) x += __shfl_xor_sync(~0u,x,o);
        if (lane==0) sred[0]=x; }
    __syncthreads();
    float inv = 1.f/sred[0];
    for (int n=tid; n<NTOK; n+=256){
        float st = in[n];
        g_state[bi*NTOK+n] = sgnf(st)*expf(fabsf(st)-m)*inv;
    }
}

// ---------------- MLP fc1 + gelu: (rows,256)->(rows,512) ----------------------
__global__ void k_mlp1(const float* __restrict__ W1, const float* __restrict__ b1, int layer){
    __shared__ __align__(16) float sA[8*DIMK];
    int row0 = blockIdx.x*8;
    for (int e=threadIdx.x; e<8*DIMK; e+=256){
        int row = row0 + (e>>8);
        sA[e] = (row<ROWS) ? g_val2[row*DIMK + (e&255)] : 0.f;
    }
    __syncthreads();
    int j = threadIdx.x;
    const float* W = W1 + layer*(DIMK*HID);
    float acc0[8]={0,0,0,0,0,0,0,0}, acc1[8]={0,0,0,0,0,0,0,0};
    for (int d=0; d<DIMK; d+=2){
        float w00=W[(d+0)*HID+j],     w01=W[(d+1)*HID+j];
        float w10=W[(d+0)*HID+j+256], w11=W[(d+1)*HID+j+256];
        #pragma unroll
        for (int i=0;i<8;i++){
            float2 av = *(const float2*)&sA[i*DIMK+d];
            acc0[i] = fmaf(av.x,w00, fmaf(av.y,w01, acc0[i]));
            acc1[i] = fmaf(av.x,w10, fmaf(av.y,w11, acc1[i]));
        }
    }
    float bb0 = b1[layer*HID+j], bb1 = b1[layer*HID+j+256];
    #pragma unroll
    for (int i=0;i<8;i++){
        int row = row0 + i; if (row>=ROWS) break;
        g_h[row*HID+j]     = geluf(acc0[i] + bb0);
        g_h[row*HID+j+256] = geluf(acc1[i] + bb1);
    }
}

// ---------------- MLP fc2 + residual + unit-norm -------------------------------
__global__ void k_mlp2(const float* __restrict__ W2, const float* __restrict__ b2, int layer){
    __shared__ __align__(16) float sH[8*HID];
    __shared__ float sSum[8];
    int row0 = blockIdx.x*8;
    for (int e=threadIdx.x; e<8*HID; e+=256){
        int row = row0 + (e>>9);
        sH[e] = (row<ROWS) ? g_h[row*HID + (e&511)] : 0.f;
    }
    if (threadIdx.x<8) sSum[threadIdx.x] = 0.f;
    __syncthreads();
    int j = threadIdx.x;
    const float* W = W2 + layer*(HID*DIMK);
    float acc[8] = {0,0,0,0,0,0,0,0};
    for (int d=0; d<HID; d+=2){
        float w0 = W[(d+0)*DIMK+j], w1 = W[(d+1)*DIMK+j];
        #pragma unroll
        for (int i=0;i<8;i++){
            float2 hv = *(const float2*)&sH[i*HID+d];
            acc[i] = fmaf(hv.x,w0, fmaf(hv.y,w1, acc[i]));
        }
    }
    float bv = b2[layer*DIMK+j];
    int lane = j & 31;
    float upd[8];
    int nv = min(8, ROWS-row0);
    for (int i=0; i<nv; i++){
        int row = row0 + i;
        upd[i] = g_val2[row*DIMK+j] + acc[i] + bv;
        float s2 = upd[i]*upd[i];
        #pragma unroll
        for (int o=16;o;o>>=1) s2 += __shfl_xor_sync(~0u,s2,o);
        if (lane==0) atomicAdd(&sSum[i], s2);
    }
    __syncthreads();
    for (int i=0; i<nv; i++){
        int row = row0 + i;
        g_val[row*DIMK+j] = upd[i] / fmaxf(sqrtf(sSum[i]), EPSV);
    }
}

// ---------------- pack output: (state, val) ------------------------------------
__global__ void k_out(float* __restrict__ out){
    const int total = ROWS + ROWS*DIMK;
    for (int i = blockIdx.x*blockDim.x + threadIdx.x; i < total; i += gridDim.x*blockDim.x)
        out[i] = (i < ROWS) ? g_state[i] : g_val[i-ROWS];
}

extern "C" void kernel_launch(void* const* d_in, const int* in_sizes, int n_in,
                              void* d_out, int out_size){
    const int*   ids = (const int*)  d_in[0];
    const float* emb = (const float*)d_in[1];
    const float* pos = (const float*)d_in[2];
    const float* av  = (const float*)d_in[3];
    const float* as  = (const float*)d_in[4];
    const float* Ws  = (const float*)d_in[5];
    const float* bs  = (const float*)d_in[6];
    const float* U   = (const float*)d_in[7];
    const float* V   = (const float*)d_in[8];
    const float* W1  = (const float*)d_in[9];
    const float* b1  = (const float*)d_in[10];
    const float* W2  = (const float*)d_in[11];
    const float* b2  = (const float*)d_in[12];

    size_t smem = ATTN_SMEM_FLOATS * sizeof(float);
    cudaFuncSetAttribute(k_attn, cudaFuncAttributeMaxDynamicSharedMemorySize, (int)smem);

    k_embed<<<BATCH*NTOK, 256>>>(ids, emb, pos, av, as, Ws, bs);
    int rb = (ROWS + 7)/8;
    dim3 ga((NTOK + 7)/8, BATCH);
    for (int l=0; l<NLAYERS; l++){
        k_qk  <<<rb, 256>>>(U, V, l);
        k_attn<<<ga, 256, smem>>>();
        k_state_sm<<<BATCH, 256>>>();
        k_mlp1<<<rb, 256>>>(W1, b1, l);
        k_mlp2<<<rb, 256>>>(W2, b2, l);
    }
    k_out<<<514, 256>>>((float*)d_out);
}